// round 1
// baseline (speedup 1.0000x reference)
#include <cuda_runtime.h>
#include <cuda_bf16.h>
#include <mma.h>
#include <cstdint>

using namespace nvcuda;

#define EPS_BN 1e-5f

// ---------------- static device workspace (no allocations allowed) ----------------
// A0: layer-1 input, K padded 784->832.  A1/A2: ping-pong activations (K=1024).
__device__ __align__(256) int8_t g_A0[32768u * 832u];
__device__ __align__(256) int8_t g_A1[32768u * 1024u];
__device__ __align__(256) int8_t g_A2[32768u * 1024u];
__device__ __align__(256) int8_t g_W1[1024u * 832u];
__device__ __align__(256) int8_t g_W2[1024u * 1024u];
__device__ __align__(256) int8_t g_W3[1024u * 1024u];
__device__ __align__(256) int8_t g_W4[10u * 1024u];

// ---------------- sign-pack: float -> int8 {+1,-1}, zero-padded to KP ----------------
__global__ void sign_pack(const float* __restrict__ src, int8_t* __restrict__ dst,
                          int rows, int K, int KP) {
    int i = blockIdx.x * 256 + threadIdx.x;
    if (i >= rows * KP) return;
    int r = i / KP;
    int c = i - r * KP;
    int8_t v = 0;
    if (c < K) v = (src[r * K + c] >= 0.0f) ? (int8_t)1 : (int8_t)-1;
    dst[i] = v;
}

// ---------------- fused binary GEMM + BN + sign ----------------
// C[m,n] = sum_k A[m,k]*W[n,k]  (s8 x s8 -> s32, exact)
// y = scale[n]*C + shift[n] ;  Aout[m,n] = sign(y)  (clip doesn't change sign)
#define BM 128
#define BN 128
#define BK 64
#define LDS_PAD 80   // byte stride for staged s8 tiles (multiple of 16; conflict-free LDSM)
#define LDC 132      // int stride for staged C tile

__global__ void __launch_bounds__(256, 2)
bgemm_bn_sign(const int8_t* __restrict__ A,
              const int8_t* __restrict__ W,
              int KP,
              const float* __restrict__ bias,
              const float* __restrict__ gamma,
              const float* __restrict__ beta,
              const float* __restrict__ mean,
              const float* __restrict__ var,
              int8_t* __restrict__ Aout) {
    extern __shared__ char sm[];
    char* smA = sm;                       // [BM][LDS_PAD]
    char* smB = sm + BM * LDS_PAD;        // [BN][LDS_PAD]
    int*  smC = (int*)sm;                 // [BM][LDC]  (reused after k-loop)
    __shared__ float s_scale[BN];
    __shared__ float s_shift[BN];

    const int t      = threadIdx.x;
    const int wid    = t >> 5;
    const int warp_m = wid >> 2;          // 0..1  -> 64 rows each
    const int warp_n = wid & 3;           // 0..3  -> 32 cols each
    const int row0   = blockIdx.y * BM;
    const int col0   = blockIdx.x * BN;

    if (t < BN) {
        int j = col0 + t;
        float sv = gamma[j] * rsqrtf(var[j] + EPS_BN);
        s_scale[t] = sv;
        s_shift[t] = sv * (bias[j] - mean[j]) + beta[j];
    }

    wmma::fragment<wmma::accumulator, 16, 16, 16, int> cf[4][2];
#pragma unroll
    for (int i = 0; i < 4; ++i)
#pragma unroll
        for (int j = 0; j < 2; ++j)
            wmma::fill_fragment(cf[i][j], 0);

    for (int kt = 0; kt < KP; kt += BK) {
        // stage A (128x64B) and B (128x64B); 512 int4 each, 2 per thread
#pragma unroll
        for (int l = 0; l < 2; ++l) {
            int idx = t + l * 256;        // 0..511
            int r   = idx >> 2;
            int c16 = (idx & 3) << 4;
            *(int4*)(smA + r * LDS_PAD + c16) =
                *(const int4*)(A + (size_t)(row0 + r) * KP + kt + c16);
            *(int4*)(smB + r * LDS_PAD + c16) =
                *(const int4*)(W + (size_t)(col0 + r) * KP + kt + c16);
        }
        __syncthreads();

#pragma unroll
        for (int ks = 0; ks < BK; ks += 16) {
            wmma::fragment<wmma::matrix_a, 16, 16, 16, signed char, wmma::row_major> af[4];
            wmma::fragment<wmma::matrix_b, 16, 16, 16, signed char, wmma::col_major> bf[2];
#pragma unroll
            for (int i = 0; i < 4; ++i)
                wmma::load_matrix_sync(af[i],
                    (const signed char*)(smA + (warp_m * 64 + i * 16) * LDS_PAD + ks), LDS_PAD);
#pragma unroll
            for (int j = 0; j < 2; ++j)
                wmma::load_matrix_sync(bf[j],
                    (const signed char*)(smB + (warp_n * 32 + j * 16) * LDS_PAD + ks), LDS_PAD);
#pragma unroll
            for (int i = 0; i < 4; ++i)
#pragma unroll
                for (int j = 0; j < 2; ++j)
                    wmma::mma_sync(cf[i][j], af[i], bf[j], cf[i][j]);
        }
        __syncthreads();
    }

    // spill accumulators to smem so the epilogue sees a plain (row,col) layout
#pragma unroll
    for (int i = 0; i < 4; ++i)
#pragma unroll
        for (int j = 0; j < 2; ++j)
            wmma::store_matrix_sync(smC + (warp_m * 64 + i * 16) * LDC + warp_n * 32 + j * 16,
                                    cf[i][j], LDC, wmma::mem_row_major);
    __syncthreads();

    // BN + sign -> int8, char4 stores (next layer K is always 1024)
#pragma unroll
    for (int it = 0; it < 16; ++it) {
        int idx4 = t + it * 256;          // 0..4095 char4 = 16384 outputs
        int r    = idx4 >> 5;
        int c4   = (idx4 & 31) << 2;
        char4 v;
        {
            float y;
            y = s_scale[c4 + 0] * (float)smC[r * LDC + c4 + 0] + s_shift[c4 + 0];
            v.x = (y >= 0.0f) ? 1 : -1;
            y = s_scale[c4 + 1] * (float)smC[r * LDC + c4 + 1] + s_shift[c4 + 1];
            v.y = (y >= 0.0f) ? 1 : -1;
            y = s_scale[c4 + 2] * (float)smC[r * LDC + c4 + 2] + s_shift[c4 + 2];
            v.z = (y >= 0.0f) ? 1 : -1;
            y = s_scale[c4 + 3] * (float)smC[r * LDC + c4 + 3] + s_shift[c4 + 3];
            v.w = (y >= 0.0f) ? 1 : -1;
        }
        *(char4*)(Aout + (size_t)(row0 + r) * 1024 + col0 + c4) = v;
    }
}

// ---------------- layer 4: N=10, warp-per-row dp4a + BN ----------------
__global__ void final_layer(const int8_t* __restrict__ A,
                            const int8_t* __restrict__ W,
                            const float* __restrict__ bias,
                            const float* __restrict__ gamma,
                            const float* __restrict__ beta,
                            const float* __restrict__ mean,
                            const float* __restrict__ var,
                            float* __restrict__ out) {
    int wid  = threadIdx.x >> 5;
    int lane = threadIdx.x & 31;
    int row  = blockIdx.x * 8 + wid;

    const int* ar = (const int*)(A + (size_t)row * 1024);   // 256 ints
    const int* wr = (const int*)W;

    int acc[10];
#pragma unroll
    for (int j = 0; j < 10; ++j) acc[j] = 0;

#pragma unroll
    for (int kb = 0; kb < 8; ++kb) {
        int k  = lane + kb * 32;
        int av = ar[k];
#pragma unroll
        for (int j = 0; j < 10; ++j)
            acc[j] = __dp4a(av, wr[j * 256 + k], acc[j]);
    }
#pragma unroll
    for (int j = 0; j < 10; ++j) {
#pragma unroll
        for (int o = 16; o > 0; o >>= 1)
            acc[j] += __shfl_xor_sync(0xffffffffu, acc[j], o);
    }
    if (lane < 10) {
        float sv = gamma[lane] * rsqrtf(var[lane] + EPS_BN);
        out[(size_t)row * 10 + lane] =
            sv * ((float)acc[lane] + bias[lane] - mean[lane]) + beta[lane];
    }
}

// ---------------- launch ----------------
extern "C" void kernel_launch(void* const* d_in, const int* in_sizes, int n_in,
                              void* d_out, int out_size) {
    const float* x  = (const float*)d_in[0];
    const float* W1 = (const float*)d_in[1];
    const float* b1 = (const float*)d_in[2];
    const float* g1 = (const float*)d_in[3];
    const float* be1= (const float*)d_in[4];
    const float* m1 = (const float*)d_in[5];
    const float* v1 = (const float*)d_in[6];
    const float* W2 = (const float*)d_in[7];
    const float* b2 = (const float*)d_in[8];
    const float* g2 = (const float*)d_in[9];
    const float* be2= (const float*)d_in[10];
    const float* m2 = (const float*)d_in[11];
    const float* v2 = (const float*)d_in[12];
    const float* W3 = (const float*)d_in[13];
    const float* b3 = (const float*)d_in[14];
    const float* g3 = (const float*)d_in[15];
    const float* be3= (const float*)d_in[16];
    const float* m3 = (const float*)d_in[17];
    const float* v3 = (const float*)d_in[18];
    const float* W4 = (const float*)d_in[19];
    const float* b4 = (const float*)d_in[20];
    const float* g4 = (const float*)d_in[21];
    const float* be4= (const float*)d_in[22];
    const float* m4 = (const float*)d_in[23];
    const float* v4 = (const float*)d_in[24];

    int8_t *a0, *a1, *a2, *w1, *w2, *w3, *w4;
    cudaGetSymbolAddress((void**)&a0, g_A0);
    cudaGetSymbolAddress((void**)&a1, g_A1);
    cudaGetSymbolAddress((void**)&a2, g_A2);
    cudaGetSymbolAddress((void**)&w1, g_W1);
    cudaGetSymbolAddress((void**)&w2, g_W2);
    cudaGetSymbolAddress((void**)&w3, g_W3);
    cudaGetSymbolAddress((void**)&w4, g_W4);

    const int M = 32768;

    sign_pack<<<(M * 832 + 255) / 256, 256>>>(x, a0, M, 784, 832);
    sign_pack<<<(1024 * 832 + 255) / 256, 256>>>(W1, w1, 1024, 784, 832);
    sign_pack<<<(1024 * 1024 + 255) / 256, 256>>>(W2, w2, 1024, 1024, 1024);
    sign_pack<<<(1024 * 1024 + 255) / 256, 256>>>(W3, w3, 1024, 1024, 1024);
    sign_pack<<<(10 * 1024 + 255) / 256, 256>>>(W4, w4, 10, 1024, 1024);

    const int SMEM = 128 * LDC * 4;   // 67584 bytes (covers staging region too)
    cudaFuncSetAttribute(bgemm_bn_sign, cudaFuncAttributeMaxDynamicSharedMemorySize, SMEM);

    dim3 grid(8, M / 128);  // x = N tiles (fast-varying -> A-tile L2 reuse), y = M tiles

    bgemm_bn_sign<<<grid, 256, SMEM>>>(a0, w1, 832,  b1, g1, be1, m1, v1, a1);
    bgemm_bn_sign<<<grid, 256, SMEM>>>(a1, w2, 1024, b2, g2, be2, m2, v2, a2);
    bgemm_bn_sign<<<grid, 256, SMEM>>>(a2, w3, 1024, b3, g3, be3, m3, v3, a1);

    final_layer<<<M / 8, 256>>>(a1, w4, b4, g4, be4, m4, v4, (float*)d_out);
}

// round 3
// speedup vs baseline: 1.8680x; 1.8680x over previous
#include <cuda_runtime.h>
#include <cuda_bf16.h>
#include <cstdint>

#define EPS_BN 1e-5f

// ===================== helpers (arch-neutral PTX only: sm_80-era) =====================
__device__ __forceinline__ uint32_t smem_to_u32(const void* p) {
    uint32_t a;
    asm("{ .reg .u64 t; cvta.to.shared.u64 t, %1; cvt.u32.u64 %0, t; }" : "=r"(a) : "l"(p));
    return a;
}
__device__ __forceinline__ void cp16(uint32_t dst, const void* src) {
    asm volatile("cp.async.cg.shared.global [%0], [%1], 16;\n" :: "r"(dst), "l"(src));
}
#define CP_COMMIT() asm volatile("cp.async.commit_group;\n" ::: "memory")
#define CP_WAIT(N)  asm volatile("cp.async.wait_group %0;\n" :: "n"(N) : "memory")

#define LDSM_X4(r, addr) \
    asm volatile("ldmatrix.sync.aligned.m8n8.x4.shared.b16 {%0,%1,%2,%3}, [%4];" \
        : "=r"((r)[0]), "=r"((r)[1]), "=r"((r)[2]), "=r"((r)[3]) : "r"(addr))

#define MMA_S8(c, a0, a1, a2, a3, b0, b1) \
    asm volatile("mma.sync.aligned.m16n8k32.row.col.s32.s8.s8.s32 " \
        "{%0,%1,%2,%3}, {%4,%5,%6,%7}, {%8,%9}, {%0,%1,%2,%3};" \
        : "+r"((c)[0]), "+r"((c)[1]), "+r"((c)[2]), "+r"((c)[3]) \
        : "r"(a0), "r"(a1), "r"(a2), "r"(a3), "r"(b0), "r"(b1))

// ===================== static device workspace =====================
__device__ __align__(256) int8_t g_A0[32768u * 832u];
__device__ __align__(256) int8_t g_A1[32768u * 1024u];
__device__ __align__(256) int8_t g_A2[32768u * 1024u];
__device__ __align__(256) int8_t g_W1[1024u * 832u];
__device__ __align__(256) int8_t g_W2[1024u * 1024u];
__device__ __align__(256) int8_t g_W3[1024u * 1024u];
__device__ __align__(256) int8_t g_W4[10u * 1024u];

// ===================== sign-pack =====================
__global__ void sign_pack(const float* __restrict__ src, int8_t* __restrict__ dst,
                          int rows, int K, int KP) {
    int i = blockIdx.x * 256 + threadIdx.x;
    if (i >= rows * KP) return;
    int r = i / KP;
    int c = i - r * KP;
    int8_t v = 0;
    if (c < K) v = (src[r * K + c] >= 0.0f) ? (int8_t)1 : (int8_t)-1;
    dst[i] = v;
}

// ===================== pipelined s8 GEMM + BN + sign =====================
// CTA 128x128x64, 8 warps (warp tile 64x32), 3-stage cp.async pipeline.
// smem: 3 stages of (A 128x80 + B 128x80) = 61440 B; reused as smC 128x132 int.
#define ST_BYTES 20480            // one stage: A(10240) + B(10240)
#define NSTAGE   3
#define LDS_ROW  80               // byte stride of s8 rows (conflict-free LDSM)
#define LDC      132
#define SM_TOTAL (128 * LDC * 4)  // 67584 (covers 3 stages = 61440 too)

__global__ void __launch_bounds__(256, 2)
bgemm_mma(const int8_t* __restrict__ A, const int8_t* __restrict__ W, int KP,
          const float* __restrict__ bias, const float* __restrict__ gamma,
          const float* __restrict__ beta, const float* __restrict__ mean,
          const float* __restrict__ var, int8_t* __restrict__ Aout) {
    extern __shared__ char smc[];
    __shared__ float s_scale[128];
    __shared__ float s_shift[128];

    const int t    = threadIdx.x;
    const int lane = t & 31;
    const int wid  = t >> 5;
    const int warp_m = wid & 1;          // 2 warp-rows of 64
    const int warp_n = wid >> 1;         // 4 warp-cols of 32
    const int row0 = blockIdx.y * 128;
    const int col0 = blockIdx.x * 128;
    const uint32_t smem_base = smem_to_u32(smc);

    if (t < 128) {
        int j = col0 + t;
        float sv = gamma[j] * rsqrtf(var[j] + EPS_BN);
        s_scale[t] = sv;
        s_shift[t] = sv * (bias[j] - mean[j]) + beta[j];
    }

    // per-thread cp.async coords: 512 16B chunks per operand per stage, 2 each
    const int lr = t >> 2;               // base row (0..63), +64 for second chunk
    const int lc = (t & 3) << 4;         // byte offset in 64B k-slab

    const int8_t* gAb = A + (size_t)row0 * KP;
    const int8_t* gBb = W + (size_t)col0 * KP;

    int acc[4][4][4];
#pragma unroll
    for (int i = 0; i < 4; ++i)
#pragma unroll
        for (int j = 0; j < 4; ++j)
#pragma unroll
            for (int k = 0; k < 4; ++k) acc[i][j][k] = 0;

    const int NK = KP >> 6;

    // ldmatrix per-lane address components
    const int a_row  = warp_m * 64 + (lane & 15);
    const int b_row  = warp_n * 32 + (lane & 15);
    const int k_off  = (lane >> 4) * 16;

#define ISSUE(kt) do {                                                        \
        int _st = (kt) % NSTAGE;                                              \
        uint32_t _sA = smem_base + _st * ST_BYTES;                            \
        uint32_t _sB = _sA + 10240;                                           \
        const int8_t* _gA = gAb + (kt) * 64;                                  \
        const int8_t* _gB = gBb + (kt) * 64;                                  \
        _Pragma("unroll")                                                     \
        for (int _l = 0; _l < 2; ++_l) {                                      \
            int _r = lr + _l * 64;                                            \
            cp16(_sA + _r * LDS_ROW + lc, _gA + (size_t)_r * KP + lc);        \
            cp16(_sB + _r * LDS_ROW + lc, _gB + (size_t)_r * KP + lc);        \
        }                                                                     \
    } while (0)

    ISSUE(0); CP_COMMIT();
    ISSUE(1); CP_COMMIT();

    for (int kt = 0; kt < NK; ++kt) {
        CP_WAIT(1);
        __syncthreads();
        if (kt + 2 < NK) { ISSUE(kt + 2); }
        CP_COMMIT();

        const int st = kt % NSTAGE;
        const uint32_t sA = smem_base + st * ST_BYTES + a_row * LDS_ROW + k_off;
        const uint32_t sB = smem_base + st * ST_BYTES + 10240 + b_row * LDS_ROW + k_off;

#pragma unroll
        for (int s = 0; s < 2; ++s) {             // two k=32 steps
            uint32_t af[4][4];
#pragma unroll
            for (int mf = 0; mf < 4; ++mf)
                LDSM_X4(af[mf], sA + mf * 16 * LDS_ROW + s * 32);
            uint32_t bf[2][4];
#pragma unroll
            for (int p = 0; p < 2; ++p)
                LDSM_X4(bf[p], sB + p * 16 * LDS_ROW + s * 32);
#pragma unroll
            for (int mf = 0; mf < 4; ++mf)
#pragma unroll
                for (int nf = 0; nf < 4; ++nf)
                    MMA_S8(acc[mf][nf],
                           af[mf][0], af[mf][1], af[mf][2], af[mf][3],
                           bf[nf >> 1][nf & 1], bf[nf >> 1][(nf & 1) + 2]);
        }
    }

    CP_WAIT(0);
    __syncthreads();

    // spill accumulators to smem in plain (row, col) layout
    {
        int* smC = (int*)smc;
        const int rbase = warp_m * 64 + (lane >> 2);
        const int cbase = warp_n * 32 + (lane & 3) * 2;
#pragma unroll
        for (int mf = 0; mf < 4; ++mf)
#pragma unroll
            for (int nf = 0; nf < 4; ++nf) {
                int r = rbase + mf * 16;
                int c = cbase + nf * 8;
                *(int2*)&smC[r * LDC + c]       = make_int2(acc[mf][nf][0], acc[mf][nf][1]);
                *(int2*)&smC[(r + 8) * LDC + c] = make_int2(acc[mf][nf][2], acc[mf][nf][3]);
            }
    }
    __syncthreads();

    // BN + sign -> packed int8 (next layer K is always 1024)
    {
        const int* smC = (const int*)smc;
#pragma unroll
        for (int it = 0; it < 16; ++it) {
            int idx4 = t + it * 256;              // 4096 char4 = 16384 outputs
            int r    = idx4 >> 5;
            int c4   = (idx4 & 31) << 2;
            uint32_t w = 0;
#pragma unroll
            for (int k = 0; k < 4; ++k) {
                float y = s_scale[c4 + k] * (float)smC[r * LDC + c4 + k] + s_shift[c4 + k];
                w |= (y >= 0.0f ? 0x01u : 0xFFu) << (8 * k);
            }
            *(uint32_t*)(Aout + (size_t)(row0 + r) * 1024 + col0 + c4) = w;
        }
    }
}

// ===================== layer 4: N=10, warp-per-row dp4a + BN =====================
__global__ void final_layer(const int8_t* __restrict__ A,
                            const int8_t* __restrict__ W,
                            const float* __restrict__ bias,
                            const float* __restrict__ gamma,
                            const float* __restrict__ beta,
                            const float* __restrict__ mean,
                            const float* __restrict__ var,
                            float* __restrict__ out) {
    int wid  = threadIdx.x >> 5;
    int lane = threadIdx.x & 31;
    int row  = blockIdx.x * 8 + wid;

    const int* ar = (const int*)(A + (size_t)row * 1024);
    const int* wr = (const int*)W;

    int acc[10];
#pragma unroll
    for (int j = 0; j < 10; ++j) acc[j] = 0;
#pragma unroll
    for (int kb = 0; kb < 8; ++kb) {
        int k  = lane + kb * 32;
        int av = ar[k];
#pragma unroll
        for (int j = 0; j < 10; ++j)
            acc[j] = __dp4a(av, wr[j * 256 + k], acc[j]);
    }
#pragma unroll
    for (int j = 0; j < 10; ++j)
#pragma unroll
        for (int o = 16; o > 0; o >>= 1)
            acc[j] += __shfl_xor_sync(0xffffffffu, acc[j], o);
    if (lane < 10) {
        float sv = gamma[lane] * rsqrtf(var[lane] + EPS_BN);
        out[(size_t)row * 10 + lane] =
            sv * ((float)acc[lane] + bias[lane] - mean[lane]) + beta[lane];
    }
}

// ===================== launch =====================
extern "C" void kernel_launch(void* const* d_in, const int* in_sizes, int n_in,
                              void* d_out, int out_size) {
    const float* x  = (const float*)d_in[0];
    const float* W1 = (const float*)d_in[1];
    const float* b1 = (const float*)d_in[2];
    const float* g1 = (const float*)d_in[3];
    const float* be1= (const float*)d_in[4];
    const float* m1 = (const float*)d_in[5];
    const float* v1 = (const float*)d_in[6];
    const float* W2 = (const float*)d_in[7];
    const float* b2 = (const float*)d_in[8];
    const float* g2 = (const float*)d_in[9];
    const float* be2= (const float*)d_in[10];
    const float* m2 = (const float*)d_in[11];
    const float* v2 = (const float*)d_in[12];
    const float* W3 = (const float*)d_in[13];
    const float* b3 = (const float*)d_in[14];
    const float* g3 = (const float*)d_in[15];
    const float* be3= (const float*)d_in[16];
    const float* m3 = (const float*)d_in[17];
    const float* v3 = (const float*)d_in[18];
    const float* W4 = (const float*)d_in[19];
    const float* b4 = (const float*)d_in[20];
    const float* g4 = (const float*)d_in[21];
    const float* be4= (const float*)d_in[22];
    const float* m4 = (const float*)d_in[23];
    const float* v4 = (const float*)d_in[24];

    int8_t *a0, *a1, *a2, *w1, *w2, *w3, *w4;
    cudaGetSymbolAddress((void**)&a0, g_A0);
    cudaGetSymbolAddress((void**)&a1, g_A1);
    cudaGetSymbolAddress((void**)&a2, g_A2);
    cudaGetSymbolAddress((void**)&w1, g_W1);
    cudaGetSymbolAddress((void**)&w2, g_W2);
    cudaGetSymbolAddress((void**)&w3, g_W3);
    cudaGetSymbolAddress((void**)&w4, g_W4);

    const int M = 32768;

    sign_pack<<<(M * 832 + 255) / 256, 256>>>(x, a0, M, 784, 832);
    sign_pack<<<(1024 * 832 + 255) / 256, 256>>>(W1, w1, 1024, 784, 832);
    sign_pack<<<(1024 * 1024 + 255) / 256, 256>>>(W2, w2, 1024, 1024, 1024);
    sign_pack<<<(1024 * 1024 + 255) / 256, 256>>>(W3, w3, 1024, 1024, 1024);
    sign_pack<<<(10 * 1024 + 255) / 256, 256>>>(W4, w4, 10, 1024, 1024);

    cudaFuncSetAttribute(bgemm_mma, cudaFuncAttributeMaxDynamicSharedMemorySize, SM_TOTAL);

    dim3 grid(8, M / 128);   // x = N tiles, y = M tiles

    bgemm_mma<<<grid, 256, SM_TOTAL>>>(a0, w1, 832,  b1, g1, be1, m1, v1, a1);
    bgemm_mma<<<grid, 256, SM_TOTAL>>>(a1, w2, 1024, b2, g2, be2, m2, v2, a2);
    bgemm_mma<<<grid, 256, SM_TOTAL>>>(a2, w3, 1024, b3, g3, be3, m3, v3, a1);

    final_layer<<<M / 8, 256>>>(a1, w4, b4, g4, be4, m4, v4, (float*)d_out);
}